// round 3
// baseline (speedup 1.0000x reference)
#include <cuda_runtime.h>
#include <cuda_bf16.h>
#include <mma.h>
#include <math.h>

using namespace nvcuda;

#define HID 128
#define NHEAD 4
#define CDIM 128
#define HC 512          // NHEAD * CDIM
#define NLAYER 3
#define NMAX 10240
#define BMAX 64

// ---------------- device scratch (static, no allocation) ----------------
static __device__ float g_h   [(size_t)NMAX * HID];   // node features (residual stream)
static __device__ float g_hw  [(size_t)NMAX * HC];    // h @ W  -> [N, H, C]
static __device__ __nv_bfloat16 g_Ahi[(size_t)NMAX * HID];
static __device__ __nv_bfloat16 g_Alo[(size_t)NMAX * HID];
static __device__ __nv_bfloat16 g_Whi[(size_t)NLAYER * HID * HC];
static __device__ __nv_bfloat16 g_Wlo[(size_t)NLAYER * HID * HC];
static __device__ float g_asrc[NMAX * NHEAD];
static __device__ float g_adst[NMAX * NHEAD];
static __device__ float g_gmax[NHEAD];                // global max of a_src per head
static __device__ float g_sum [NMAX * NHEAD];
static __device__ float g_out [(size_t)NMAX * HID];   // aggregated (head-mean) output
static __device__ float g_pool[BMAX * HID];
static __device__ float g_cnt [BMAX];
static __device__ int   g_is64;

// ---------------- helpers ----------------
__device__ __forceinline__ float lrelu(float x) { return x > 0.f ? x : 0.2f * x; }

__device__ __forceinline__ void atomicMaxF(float* a, float v) {
    if (v >= 0.f) atomicMax((int*)a, __float_as_int(v));
    else          atomicMin((unsigned int*)a, __float_as_uint(v));
}

__device__ __forceinline__ void redAdd4(float* p, float4 v) {
    asm volatile("red.global.add.v4.f32 [%0], {%1,%2,%3,%4};"
                 :: "l"(p), "f"(v.x), "f"(v.y), "f"(v.z), "f"(v.w) : "memory");
}

__device__ __forceinline__ int idx_at(const void* p, int i, int is64) {
    return is64 ? (int)((const long long*)p)[i] : ((const int*)p)[i];
}

__global__ void k_detect(const void* ei, int M) {
    const long long* p = (const long long*)ei;
    int ok = 1;
    for (int i = 0; i < 16; i++) {
        long long v = p[i];
        if (v < 0 || v >= (long long)M) { ok = 0; break; }
    }
    g_is64 = ok;
}

// ---------------- kernels ----------------

// h0 = relu(x @ node_W + node_b), x:[N,5], node_W:[5,128]
__global__ void k_init(const float* __restrict__ x, const float* __restrict__ W,
                       const float* __restrict__ b, int M) {
    int i = blockIdx.x * blockDim.x + threadIdx.x;
    if (i >= M * HID) return;
    int n = i >> 7, j = i & 127;
    float acc = b[j];
#pragma unroll
    for (int k = 0; k < 5; k++) acc += x[n * 5 + k] * W[k * HID + j];
    g_h[i] = fmaxf(acc, 0.f);
}

// split all layer weights to bf16 hi/lo (once)
__global__ void k_convW(const float* __restrict__ Ws) {
    int i = blockIdx.x * blockDim.x + threadIdx.x;
    if (i >= NLAYER * HID * HC) return;
    float w = Ws[i];
    __nv_bfloat16 hi = __float2bfloat16(w);
    g_Whi[i] = hi;
    g_Wlo[i] = __float2bfloat16(w - __bfloat162float(hi));
}

// per-layer prep: split h to bf16 hi/lo, zero g_out, g_sum, g_gmax
__global__ void k_prep(int M) {
    int i = blockIdx.x * blockDim.x + threadIdx.x;
    if (i >= M * HID) return;
    float h = g_h[i];
    __nv_bfloat16 hi = __float2bfloat16(h);
    g_Ahi[i] = hi;
    g_Alo[i] = __float2bfloat16(h - __bfloat162float(hi));
    g_out[i] = 0.f;
    if (i < M * NHEAD) g_sum[i] = 0.f;
    if (i < NHEAD) g_gmax[i] = -1e30f;
}

// GEMM: hw = h @ W via bf16x3 tensor-core mma. Block computes 64(M) x 128(N=one head).
// Epilogue: writes g_hw, computes a_src/a_dst row dots for this head, atomicMax gmax.
__global__ void k_gemm(const __nv_bfloat16* __restrict__ Whi,
                       const __nv_bfloat16* __restrict__ Wlo,
                       const float* __restrict__ att_src,
                       const float* __restrict__ att_dst, int M) {
    __shared__ float Cs[64][132];                 // 33.8 KB
    int head = blockIdx.x;                        // N tile = head (128 cols)
    int bm = blockIdx.y * 64;
    int tid = threadIdx.x;
    int w = tid >> 5, lane = tid & 31;
    int wm = w & 1, wn = w >> 1;                  // 2 x 4 warp grid over 64 x 128

    wmma::fragment<wmma::accumulator, 16, 16, 16, float> acc[2][2];
#pragma unroll
    for (int i = 0; i < 2; i++)
#pragma unroll
        for (int j = 0; j < 2; j++) wmma::fill_fragment(acc[i][j], 0.f);

    const __nv_bfloat16* Ahi0 = g_Ahi + (size_t)(bm + wm * 32) * HID;
    const __nv_bfloat16* Alo0 = g_Alo + (size_t)(bm + wm * 32) * HID;
    const __nv_bfloat16* Bhi0 = Whi + head * 128 + wn * 32;
    const __nv_bfloat16* Blo0 = Wlo + head * 128 + wn * 32;

#pragma unroll
    for (int ki = 0; ki < 8; ki++) {
        int k0 = ki * 16;
        wmma::fragment<wmma::matrix_a, 16, 16, 16, __nv_bfloat16, wmma::row_major> ahi[2], alo[2];
        wmma::fragment<wmma::matrix_b, 16, 16, 16, __nv_bfloat16, wmma::row_major> bhi[2], blo[2];
#pragma unroll
        for (int i = 0; i < 2; i++) {
            wmma::load_matrix_sync(ahi[i], Ahi0 + (size_t)(i * 16) * HID + k0, HID);
            wmma::load_matrix_sync(alo[i], Alo0 + (size_t)(i * 16) * HID + k0, HID);
            wmma::load_matrix_sync(bhi[i], Bhi0 + (size_t)k0 * HC + i * 16, HC);
            wmma::load_matrix_sync(blo[i], Blo0 + (size_t)k0 * HC + i * 16, HC);
        }
#pragma unroll
        for (int i = 0; i < 2; i++)
#pragma unroll
            for (int j = 0; j < 2; j++) {
                wmma::mma_sync(acc[i][j], ahi[i], bhi[j], acc[i][j]);
                wmma::mma_sync(acc[i][j], ahi[i], blo[j], acc[i][j]);
                wmma::mma_sync(acc[i][j], alo[i], bhi[j], acc[i][j]);
            }
    }

    // stage C tile in smem
#pragma unroll
    for (int i = 0; i < 2; i++)
#pragma unroll
        for (int j = 0; j < 2; j++)
            wmma::store_matrix_sync(&Cs[wm * 32 + i * 16][wn * 32 + j * 16], acc[i][j],
                                    132, wmma::mem_row_major);
    __syncthreads();

    // write out + attention dots; warp w handles rows w*8 .. w*8+7
    float4 as4 = *(const float4*)(att_src + head * CDIM + lane * 4);
    float4 ad4 = *(const float4*)(att_dst + head * CDIM + lane * 4);
#pragma unroll
    for (int r = 0; r < 8; r++) {
        int row = w * 8 + r;
        int grow = bm + row;
        if (grow >= M) break;
        float4 c4 = *(float4*)&Cs[row][lane * 4];
        *(float4*)(g_hw + (size_t)grow * HC + head * CDIM + lane * 4) = c4;
        float ss = c4.x * as4.x + c4.y * as4.y + c4.z * as4.z + c4.w * as4.w;
        float sd = c4.x * ad4.x + c4.y * ad4.y + c4.z * ad4.z + c4.w * ad4.w;
#pragma unroll
        for (int o = 16; o; o >>= 1) {
            ss += __shfl_xor_sync(~0u, ss, o);
            sd += __shfl_xor_sync(~0u, sd, o);
        }
        if (lane == 0) {
            g_asrc[grow * 4 + head] = ss;
            g_adst[grow * 4 + head] = sd;
            atomicMaxF(&g_gmax[head], ss);
        }
    }
}

// denom pass: m_d = lrelu(gmax + a_dst[d]) (valid upper bound; lrelu monotone)
__global__ void k_edge_sum(const void* __restrict__ ei, int E, int M) {
    int i = blockIdx.x * blockDim.x + threadIdx.x;
    if (i >= E + M) return;
    int is64 = g_is64;
    int s, d;
    if (i < E) { s = idx_at(ei, i, is64); d = idx_at(ei, E + i, is64); } else { s = d = i - E; }
    float4 gm = *(const float4*)g_gmax;
    float4 as = *(const float4*)(g_asrc + s * 4);
    float4 ad = *(const float4*)(g_adst + d * 4);
    atomicAdd(g_sum + d * 4 + 0, expf(lrelu(as.x + ad.x) - lrelu(gm.x + ad.x)));
    atomicAdd(g_sum + d * 4 + 1, expf(lrelu(as.y + ad.y) - lrelu(gm.y + ad.y)));
    atomicAdd(g_sum + d * 4 + 2, expf(lrelu(as.z + ad.z) - lrelu(gm.z + ad.z)));
    atomicAdd(g_sum + d * 4 + 3, expf(lrelu(as.w + ad.w) - lrelu(gm.w + ad.w)));
}

// accumulate pass: one warp per edge; head-mean folded in
__global__ void k_edge_acc(const void* __restrict__ ei, int E, int M) {
    int gid = blockIdx.x * blockDim.x + threadIdx.x;
    int w = gid >> 5, lane = gid & 31;
    if (w >= E + M) return;
    int is64 = g_is64;
    int s, d;
    if (w < E) { s = idx_at(ei, w, is64); d = idx_at(ei, E + w, is64); } else { s = d = w - E; }
    float4 gm = *(const float4*)g_gmax;
    float4 as = *(const float4*)(g_asrc + s * 4);
    float4 ad = *(const float4*)(g_adst + d * 4);
    float4 sm = *(const float4*)(g_sum + d * 4);
    float a0 = expf(lrelu(as.x + ad.x) - lrelu(gm.x + ad.x)) / (sm.x + 1e-16f) * 0.25f;
    float a1 = expf(lrelu(as.y + ad.y) - lrelu(gm.y + ad.y)) / (sm.y + 1e-16f) * 0.25f;
    float a2 = expf(lrelu(as.z + ad.z) - lrelu(gm.z + ad.z)) / (sm.z + 1e-16f) * 0.25f;
    float a3 = expf(lrelu(as.w + ad.w) - lrelu(gm.w + ad.w)) / (sm.w + 1e-16f) * 0.25f;
    const float4* hs = (const float4*)(g_hw + (size_t)s * HC);
    float4 v0 = hs[lane];
    float4 v1 = hs[32 + lane];
    float4 v2 = hs[64 + lane];
    float4 v3 = hs[96 + lane];
    float4 r;
    r.x = a0 * v0.x + a1 * v1.x + a2 * v2.x + a3 * v3.x;
    r.y = a0 * v0.y + a1 * v1.y + a2 * v2.y + a3 * v3.y;
    r.z = a0 * v0.z + a1 * v1.z + a2 * v2.z + a3 * v3.z;
    r.w = a0 * v0.w + a1 * v1.w + a2 * v2.w + a3 * v3.w;
    redAdd4(g_out + (size_t)d * HID + lane * 4, r);
}

// bias + layernorm + relu + residual. Block = 128 threads per node.
__global__ void k_post(const float* __restrict__ bias, const float* __restrict__ lng,
                       const float* __restrict__ lnb, int M) {
    int n = blockIdx.x;
    if (n >= M) return;
    int t = threadIdx.x;
    float v = g_out[(size_t)n * HID + t] + bias[t];
    __shared__ float sh[4];
    float s = v;
#pragma unroll
    for (int o = 16; o; o >>= 1) s += __shfl_xor_sync(~0u, s, o);
    if ((t & 31) == 0) sh[t >> 5] = s;
    __syncthreads();
    float mu = (sh[0] + sh[1] + sh[2] + sh[3]) * (1.f / 128.f);
    __syncthreads();
    float dv = v - mu;
    float q = dv * dv;
#pragma unroll
    for (int o = 16; o; o >>= 1) q += __shfl_xor_sync(~0u, q, o);
    if ((t & 31) == 0) sh[t >> 5] = q;
    __syncthreads();
    float var = (sh[0] + sh[1] + sh[2] + sh[3]) * (1.f / 128.f);
    float ln = dv * rsqrtf(var + 1e-5f) * lng[t] + lnb[t];
    g_h[(size_t)n * HID + t] += fmaxf(ln, 0.f);
}

__global__ void k_pool_zero() {
    int i = blockIdx.x * blockDim.x + threadIdx.x;
    if (i < BMAX * HID) g_pool[i] = 0.f;
    if (i < BMAX) g_cnt[i] = 0.f;
}

__global__ void k_pool(const void* __restrict__ batch, int M) {
    int gid = blockIdx.x * blockDim.x + threadIdx.x;
    int n = gid >> 5, lane = gid & 31;
    if (n >= M) return;
    int b = idx_at(batch, n, g_is64);
    float4 v = *(const float4*)(g_h + (size_t)n * HID + lane * 4);
    redAdd4(g_pool + b * HID + lane * 4, v);
    if (lane == 0) atomicAdd(g_cnt + b, 1.f);
}

__global__ void k_write(float* __restrict__ dout, int M, int total) {
    int i = blockIdx.x * blockDim.x + threadIdx.x;
    if (i >= total) return;
    int nh = M * HID;
    if (i < nh) {
        dout[i] = g_h[i];
    } else {
        int j = i - nh;
        dout[i] = g_pool[j] / fmaxf(g_cnt[j >> 7], 1.f);
    }
}

// ---------------- launch ----------------
extern "C" void kernel_launch(void* const* d_in, const int* in_sizes, int n_in,
                              void* d_out, int out_size) {
    const float* x        = (const float*)d_in[0];
    const void*  ei       = d_in[1];
    const void*  batch    = d_in[2];
    const float* node_W   = (const float*)d_in[3];
    const float* node_b   = (const float*)d_in[4];
    const float* Ws       = (const float*)d_in[5];
    const float* att_srcs = (const float*)d_in[6];
    const float* att_dsts = (const float*)d_in[7];
    const float* biases   = (const float*)d_in[8];
    const float* ln_gs    = (const float*)d_in[9];
    const float* ln_bs    = (const float*)d_in[10];

    int M = in_sizes[2];          // N nodes
    int E = in_sizes[1] / 2;      // edges (before self-loops)
    int EM = E + M;
    float* dout = (float*)d_out;

    k_detect<<<1, 1>>>(ei, M);
    k_init<<<(M * HID + 255) / 256, 256>>>(x, node_W, node_b, M);
    k_convW<<<(NLAYER * HID * HC + 255) / 256, 256>>>(Ws);

    __nv_bfloat16* whi_base;
    __nv_bfloat16* wlo_base;
    cudaGetSymbolAddress((void**)&whi_base, g_Whi);
    cudaGetSymbolAddress((void**)&wlo_base, g_Wlo);

    for (int l = 0; l < NLAYER; l++) {
        k_prep<<<(M * HID + 255) / 256, 256>>>(M);
        k_gemm<<<dim3(NHEAD, (M + 63) / 64), 256>>>(whi_base + (size_t)l * HID * HC,
                                                    wlo_base + (size_t)l * HID * HC,
                                                    att_srcs + l * HC, att_dsts + l * HC, M);
        k_edge_sum<<<(EM + 255) / 256, 256>>>(ei, E, M);
        k_edge_acc<<<((size_t)EM * 32 + 255) / 256, 256>>>(ei, E, M);
        k_post<<<M, 128>>>(biases + l * HID, ln_gs + l * HID, ln_bs + l * HID, M);
    }

    k_pool_zero<<<(BMAX * HID + 255) / 256, 256>>>();
    k_pool<<<((size_t)M * 32 + 255) / 256, 256>>>(batch, M);
    k_write<<<(out_size + 255) / 256, 256>>>(dout, M, out_size);
}

// round 4
// speedup vs baseline: 1.3970x; 1.3970x over previous
#include <cuda_runtime.h>
#include <cuda_bf16.h>
#include <mma.h>
#include <math.h>

using namespace nvcuda;

#define HID 128
#define NHEAD 4
#define CDIM 128
#define HC 512
#define NLAYER 3
#define NMAX 10240
#define BMAX 64
#define EMAX (160000 + NMAX + 768)

// ---------------- device scratch ----------------
static __device__ __align__(16) float g_h   [(size_t)NMAX * HID];
static __device__ __align__(16) float g_hw  [(size_t)NMAX * HC];
static __device__ __align__(16) __nv_bfloat16 g_Ahi[(size_t)NMAX * HID];
static __device__ __align__(16) __nv_bfloat16 g_Alo[(size_t)NMAX * HID];
static __device__ __align__(16) __nv_bfloat16 g_Whi[(size_t)NLAYER * HID * HC];
static __device__ __align__(16) __nv_bfloat16 g_Wlo[(size_t)NLAYER * HID * HC];
static __device__ __align__(16) float g_asrc[NMAX * NHEAD];
static __device__ __align__(16) float g_adst[NMAX * NHEAD];
static __device__ __align__(16) float g_gmax[NHEAD];
static __device__ __align__(16) float g_sum [NMAX * NHEAD];
static __device__ __align__(16) float g_out [(size_t)NMAX * HID];
static __device__ __align__(16) float g_pool[BMAX * HID];
static __device__ float g_cnt [BMAX];
static __device__ int   g_is64;
// CSR by src
static __device__ int g_deg[NMAX];
static __device__ int g_ptr[NMAX];
static __device__ int g_cur[NMAX];
static __device__ int g_adj[EMAX];

// ---------------- helpers ----------------
__device__ __forceinline__ float lrelu(float x) { return x > 0.f ? x : 0.2f * x; }

__device__ __forceinline__ void atomicMaxF(float* a, float v) {
    if (v >= 0.f) atomicMax((int*)a, __float_as_int(v));
    else          atomicMin((unsigned int*)a, __float_as_uint(v));
}

__device__ __forceinline__ void redAdd4(float* p, float4 v) {
    asm volatile("red.global.add.v4.f32 [%0], {%1,%2,%3,%4};"
                 :: "l"(p), "f"(v.x), "f"(v.y), "f"(v.z), "f"(v.w) : "memory");
}

__device__ __forceinline__ int idx_at(const void* p, int i, int is64) {
    return is64 ? (int)((const long long*)p)[i] : ((const int*)p)[i];
}

__global__ void k_detect(const void* ei, int M) {
    const long long* p = (const long long*)ei;
    int ok = 1;
    for (int i = 0; i < 16; i++) {
        long long v = p[i];
        if (v < 0 || v >= (long long)M) { ok = 0; break; }
    }
    g_is64 = ok;
}

// ---------------- CSR build ----------------
__global__ void k_csr0(int M) {
    int i = blockIdx.x * blockDim.x + threadIdx.x;
    if (i < M) g_deg[i] = 0;
}

__global__ void k_hist(const void* __restrict__ ei, int E, int M) {
    int i = blockIdx.x * blockDim.x + threadIdx.x;
    if (i >= E + M) return;
    int s = (i < E) ? idx_at(ei, i, g_is64) : (i - E);
    atomicAdd(&g_deg[s], 1);
}

__global__ void k_scan(int M) {
    __shared__ int sh[1024];
    int t = threadIdx.x;
    int chunk = (M + 1023) / 1024;
    int start = t * chunk;
    int sum = 0;
    for (int i = 0; i < chunk; i++) {
        int idx = start + i;
        if (idx < M) sum += g_deg[idx];
    }
    sh[t] = sum;
    __syncthreads();
    for (int off = 1; off < 1024; off <<= 1) {
        int v = (t >= off) ? sh[t - off] : 0;
        __syncthreads();
        sh[t] += v;
        __syncthreads();
    }
    int run = t ? sh[t - 1] : 0;
    for (int i = 0; i < chunk; i++) {
        int idx = start + i;
        if (idx < M) {
            g_ptr[idx] = run;
            g_cur[idx] = run;
            run += g_deg[idx];
        }
    }
}

__global__ void k_fill(const void* __restrict__ ei, int E, int M) {
    int i = blockIdx.x * blockDim.x + threadIdx.x;
    if (i >= E + M) return;
    int is64 = g_is64;
    int s, d;
    if (i < E) { s = idx_at(ei, i, is64); d = idx_at(ei, E + i, is64); } else { s = d = i - E; }
    int pos = atomicAdd(&g_cur[s], 1);
    g_adj[pos] = d;
}

// ---------------- kernels ----------------

// h0 = relu(x @ node_W + node_b); also split to bf16 hi/lo, zero g_out/g_sum/gmax
__global__ void k_init(const float* __restrict__ x, const float* __restrict__ W,
                       const float* __restrict__ b, int M) {
    int i = blockIdx.x * blockDim.x + threadIdx.x;
    if (i >= M * HID) return;
    int n = i >> 7, j = i & 127;
    float acc = b[j];
#pragma unroll
    for (int k = 0; k < 5; k++) acc += x[n * 5 + k] * W[k * HID + j];
    float h = fmaxf(acc, 0.f);
    g_h[i] = h;
    __nv_bfloat16 hi = __float2bfloat16(h);
    g_Ahi[i] = hi;
    g_Alo[i] = __float2bfloat16(h - __bfloat162float(hi));
    g_out[i] = 0.f;
    if (i < M * NHEAD) g_sum[i] = 0.f;
    if (i < NHEAD) g_gmax[i] = -1e30f;
}

__global__ void k_convW(const float* __restrict__ Ws) {
    int i = blockIdx.x * blockDim.x + threadIdx.x;
    if (i >= NLAYER * HID * HC) return;
    float w = Ws[i];
    __nv_bfloat16 hi = __float2bfloat16(w);
    g_Whi[i] = hi;
    g_Wlo[i] = __float2bfloat16(w - __bfloat162float(hi));
}

// GEMM: 64(M) x 128(N=head) tile, smem-staged bf16x3 wmma. Epilogue: g_hw write,
// a_src/a_dst row dots, gmax atomicMax.
__global__ void k_gemm(const __nv_bfloat16* __restrict__ Whi,
                       const __nv_bfloat16* __restrict__ Wlo,
                       const float* __restrict__ att_src,
                       const float* __restrict__ att_dst, int M) {
    __shared__ __align__(16) unsigned char sm_raw[64 * 132 * 4];  // 33792 B
    __nv_bfloat16* Ahi = (__nv_bfloat16*)sm_raw;                  // [64][48]
    __nv_bfloat16* Alo = Ahi + 64 * 48;
    __nv_bfloat16* Bhi = (__nv_bfloat16*)(sm_raw + 12288);        // [32][136]
    __nv_bfloat16* Blo = Bhi + 32 * 136;
    float* Cs = (float*)sm_raw;                                   // [64][132]

    int head = blockIdx.x;
    int bm = blockIdx.y * 64;
    int tid = threadIdx.x;
    int w = tid >> 5, lane = tid & 31;
    int wm = w & 1, wn = w >> 1;          // 2 x 4 warps over 64 x 128

    wmma::fragment<wmma::accumulator, 16, 16, 16, float> acc[2][2];
#pragma unroll
    for (int i = 0; i < 2; i++)
#pragma unroll
        for (int j = 0; j < 2; j++) wmma::fill_fragment(acc[i][j], 0.f);

    for (int k0 = 0; k0 < 128; k0 += 32) {
        // stage A chunk: 64 rows x 32 cols (hi+lo)
        {
            int row = tid >> 2, c8 = (tid & 3) * 8;
            int grow = bm + row;
            uint4 vh = make_uint4(0, 0, 0, 0), vl = make_uint4(0, 0, 0, 0);
            if (grow < M) {
                vh = *(const uint4*)(g_Ahi + (size_t)grow * HID + k0 + c8);
                vl = *(const uint4*)(g_Alo + (size_t)grow * HID + k0 + c8);
            }
            *(uint4*)(Ahi + row * 48 + c8) = vh;
            *(uint4*)(Alo + row * 48 + c8) = vl;
        }
        // stage B chunk: 32 k-rows x 128 cols (hi+lo)
#pragma unroll
        for (int i = 0; i < 2; i++) {
            int idx = tid + i * 256;
            int r = idx >> 4, c8 = (idx & 15) * 8;
            *(uint4*)(Bhi + r * 136 + c8) =
                *(const uint4*)(Whi + (size_t)(k0 + r) * HC + head * 128 + c8);
            *(uint4*)(Blo + r * 136 + c8) =
                *(const uint4*)(Wlo + (size_t)(k0 + r) * HC + head * 128 + c8);
        }
        __syncthreads();
#pragma unroll
        for (int kk = 0; kk < 32; kk += 16) {
            wmma::fragment<wmma::matrix_a, 16, 16, 16, __nv_bfloat16, wmma::row_major> ahi[2], alo[2];
            wmma::fragment<wmma::matrix_b, 16, 16, 16, __nv_bfloat16, wmma::row_major> bhi[2], blo[2];
#pragma unroll
            for (int i = 0; i < 2; i++) {
                wmma::load_matrix_sync(ahi[i], Ahi + (wm * 32 + i * 16) * 48 + kk, 48);
                wmma::load_matrix_sync(alo[i], Alo + (wm * 32 + i * 16) * 48 + kk, 48);
                wmma::load_matrix_sync(bhi[i], Bhi + kk * 136 + wn * 32 + i * 16, 136);
                wmma::load_matrix_sync(blo[i], Blo + kk * 136 + wn * 32 + i * 16, 136);
            }
#pragma unroll
            for (int i = 0; i < 2; i++)
#pragma unroll
                for (int j = 0; j < 2; j++) {
                    wmma::mma_sync(acc[i][j], ahi[i], bhi[j], acc[i][j]);
                    wmma::mma_sync(acc[i][j], ahi[i], blo[j], acc[i][j]);
                    wmma::mma_sync(acc[i][j], alo[i], bhi[j], acc[i][j]);
                }
        }
        __syncthreads();
    }

    // stage C (aliases tiles; guarded by the loop-end sync)
#pragma unroll
    for (int i = 0; i < 2; i++)
#pragma unroll
        for (int j = 0; j < 2; j++)
            wmma::store_matrix_sync(Cs + (wm * 32 + i * 16) * 132 + wn * 32 + j * 16,
                                    acc[i][j], 132, wmma::mem_row_major);
    __syncthreads();

    // epilogue: warp w handles rows w*8 .. w*8+7
    float4 as4 = *(const float4*)(att_src + head * CDIM + lane * 4);
    float4 ad4 = *(const float4*)(att_dst + head * CDIM + lane * 4);
#pragma unroll
    for (int r = 0; r < 8; r++) {
        int row = w * 8 + r;
        int grow = bm + row;
        if (grow >= M) break;
        float4 c4 = *(float4*)(Cs + row * 132 + lane * 4);
        *(float4*)(g_hw + (size_t)grow * HC + head * CDIM + lane * 4) = c4;
        float ss = c4.x * as4.x + c4.y * as4.y + c4.z * as4.z + c4.w * as4.w;
        float sd = c4.x * ad4.x + c4.y * ad4.y + c4.z * ad4.z + c4.w * ad4.w;
#pragma unroll
        for (int o = 16; o; o >>= 1) {
            ss += __shfl_xor_sync(~0u, ss, o);
            sd += __shfl_xor_sync(~0u, sd, o);
        }
        if (lane == 0) {
            g_asrc[grow * 4 + head] = ss;
            g_adst[grow * 4 + head] = sd;
            atomicMaxF(&g_gmax[head], ss);
        }
    }
}

// denom pass (edge-parallel): m_d = lrelu(gmax + a_dst[d]) upper-bound shift
__global__ void k_edge_sum(const void* __restrict__ ei, int E, int M) {
    int i = blockIdx.x * blockDim.x + threadIdx.x;
    if (i >= E + M) return;
    int is64 = g_is64;
    int s, d;
    if (i < E) { s = idx_at(ei, i, is64); d = idx_at(ei, E + i, is64); } else { s = d = i - E; }
    float4 gm = *(const float4*)g_gmax;
    float4 as = *(const float4*)(g_asrc + s * 4);
    float4 ad = *(const float4*)(g_adst + d * 4);
    atomicAdd(g_sum + d * 4 + 0, expf(lrelu(as.x + ad.x) - lrelu(gm.x + ad.x)));
    atomicAdd(g_sum + d * 4 + 1, expf(lrelu(as.y + ad.y) - lrelu(gm.y + ad.y)));
    atomicAdd(g_sum + d * 4 + 2, expf(lrelu(as.z + ad.z) - lrelu(gm.z + ad.z)));
    atomicAdd(g_sum + d * 4 + 3, expf(lrelu(as.w + ad.w) - lrelu(gm.w + ad.w)));
}

// aggregate: one warp per SRC node; hw[src] read once, red.add per neighbor
__global__ void k_acc(int M) {
    int gid = blockIdx.x * blockDim.x + threadIdx.x;
    int s = gid >> 5, lane = gid & 31;
    if (s >= M) return;
    float4 gm = *(const float4*)g_gmax;
    float4 as = *(const float4*)(g_asrc + s * 4);
    const float4* hs = (const float4*)(g_hw + (size_t)s * HC);
    float4 v0 = hs[lane];
    float4 v1 = hs[32 + lane];
    float4 v2 = hs[64 + lane];
    float4 v3 = hs[96 + lane];
    int base = g_ptr[s], cnt = g_deg[s];
    for (int j0 = 0; j0 < cnt; j0 += 32) {
        int j = j0 + lane;
        int d = 0;
        float a0 = 0.f, a1 = 0.f, a2 = 0.f, a3 = 0.f;
        if (j < cnt) {
            d = g_adj[base + j];
            float4 ad = *(const float4*)(g_adst + d * 4);
            float4 sm = *(const float4*)(g_sum + d * 4);
            a0 = expf(lrelu(as.x + ad.x) - lrelu(gm.x + ad.x)) / (sm.x + 1e-16f) * 0.25f;
            a1 = expf(lrelu(as.y + ad.y) - lrelu(gm.y + ad.y)) / (sm.y + 1e-16f) * 0.25f;
            a2 = expf(lrelu(as.z + ad.z) - lrelu(gm.z + ad.z)) / (sm.z + 1e-16f) * 0.25f;
            a3 = expf(lrelu(as.w + ad.w) - lrelu(gm.w + ad.w)) / (sm.w + 1e-16f) * 0.25f;
        }
        int m = min(cnt - j0, 32);
        for (int jj = 0; jj < m; jj++) {
            int dd  = __shfl_sync(~0u, d, jj);
            float b0 = __shfl_sync(~0u, a0, jj);
            float b1 = __shfl_sync(~0u, a1, jj);
            float b2 = __shfl_sync(~0u, a2, jj);
            float b3 = __shfl_sync(~0u, a3, jj);
            float4 r;
            r.x = b0 * v0.x + b1 * v1.x + b2 * v2.x + b3 * v3.x;
            r.y = b0 * v0.y + b1 * v1.y + b2 * v2.y + b3 * v3.y;
            r.z = b0 * v0.z + b1 * v1.z + b2 * v2.z + b3 * v3.z;
            r.w = b0 * v0.w + b1 * v1.w + b2 * v2.w + b3 * v3.w;
            redAdd4(g_out + (size_t)dd * HID + lane * 4, r);
        }
    }
}

// bias + layernorm + relu + residual; also next-layer prep (bf16 split, zeroing)
__global__ void k_post(const float* __restrict__ bias, const float* __restrict__ lng,
                       const float* __restrict__ lnb, int M, float* __restrict__ dout) {
    int n = blockIdx.x;
    if (n >= M) return;
    int t = threadIdx.x;
    size_t i = (size_t)n * HID + t;
    float v = g_out[i] + bias[t];
    __shared__ float sh[4];
    float s = v;
#pragma unroll
    for (int o = 16; o; o >>= 1) s += __shfl_xor_sync(~0u, s, o);
    if ((t & 31) == 0) sh[t >> 5] = s;
    __syncthreads();
    float mu = (sh[0] + sh[1] + sh[2] + sh[3]) * (1.f / 128.f);
    __syncthreads();
    float dv = v - mu;
    float q = dv * dv;
#pragma unroll
    for (int o = 16; o; o >>= 1) q += __shfl_xor_sync(~0u, q, o);
    if ((t & 31) == 0) sh[t >> 5] = q;
    __syncthreads();
    float var = (sh[0] + sh[1] + sh[2] + sh[3]) * (1.f / 128.f);
    float ln = dv * rsqrtf(var + 1e-5f) * lng[t] + lnb[t];
    float h = g_h[i] + fmaxf(ln, 0.f);
    g_h[i] = h;
    __nv_bfloat16 hi = __float2bfloat16(h);
    g_Ahi[i] = hi;
    g_Alo[i] = __float2bfloat16(h - __bfloat162float(hi));
    g_out[i] = 0.f;                       // prep next layer
    if (t < NHEAD) g_sum[n * NHEAD + t] = 0.f;
    if (n == 0 && t < NHEAD) g_gmax[t] = -1e30f;
    if (dout) dout[i] = h;                // final layer writes output directly
}

__global__ void k_pool_zero() {
    int i = blockIdx.x * blockDim.x + threadIdx.x;
    if (i < BMAX * HID) g_pool[i] = 0.f;
    if (i < BMAX) g_cnt[i] = 0.f;
}

__global__ void k_pool(const void* __restrict__ batch, int M) {
    int gid = blockIdx.x * blockDim.x + threadIdx.x;
    int n = gid >> 5, lane = gid & 31;
    if (n >= M) return;
    int b = idx_at(batch, n, g_is64);
    float4 v = *(const float4*)(g_h + (size_t)n * HID + lane * 4);
    redAdd4(g_pool + b * HID + lane * 4, v);
    if (lane == 0) atomicAdd(g_cnt + b, 1.f);
}

__global__ void k_write_pool(float* __restrict__ dout, int M, int tail) {
    int i = blockIdx.x * blockDim.x + threadIdx.x;
    if (i >= tail) return;
    dout[(size_t)M * HID + i] = g_pool[i] / fmaxf(g_cnt[i >> 7], 1.f);
}

// ---------------- launch ----------------
extern "C" void kernel_launch(void* const* d_in, const int* in_sizes, int n_in,
                              void* d_out, int out_size) {
    const float* x        = (const float*)d_in[0];
    const void*  ei       = d_in[1];
    const void*  batch    = d_in[2];
    const float* node_W   = (const float*)d_in[3];
    const float* node_b   = (const float*)d_in[4];
    const float* Ws       = (const float*)d_in[5];
    const float* att_srcs = (const float*)d_in[6];
    const float* att_dsts = (const float*)d_in[7];
    const float* biases   = (const float*)d_in[8];
    const float* ln_gs    = (const float*)d_in[9];
    const float* ln_bs    = (const float*)d_in[10];

    int M = in_sizes[2];
    int E = in_sizes[1] / 2;
    int EM = E + M;
    float* dout = (float*)d_out;

    k_detect<<<1, 1>>>(ei, M);
    // CSR build (by src) — reused across layers
    k_csr0<<<(M + 255) / 256, 256>>>(M);
    k_hist<<<(EM + 255) / 256, 256>>>(ei, E, M);
    k_scan<<<1, 1024>>>(M);
    k_fill<<<(EM + 255) / 256, 256>>>(ei, E, M);

    k_init<<<(M * HID + 255) / 256, 256>>>(x, node_W, node_b, M);
    k_convW<<<(NLAYER * HID * HC + 255) / 256, 256>>>(Ws);

    __nv_bfloat16* whi_base;
    __nv_bfloat16* wlo_base;
    cudaGetSymbolAddress((void**)&whi_base, g_Whi);
    cudaGetSymbolAddress((void**)&wlo_base, g_Wlo);

    for (int l = 0; l < NLAYER; l++) {
        k_gemm<<<dim3(NHEAD, (M + 63) / 64), 256>>>(whi_base + (size_t)l * HID * HC,
                                                    wlo_base + (size_t)l * HID * HC,
                                                    att_srcs + l * HC, att_dsts + l * HC, M);
        k_edge_sum<<<(EM + 255) / 256, 256>>>(ei, E, M);
        k_acc<<<((size_t)M * 32 + 255) / 256, 256>>>(M);
        k_post<<<M, 128>>>(biases + l * HID, ln_gs + l * HID, ln_bs + l * HID, M,
                           (l == NLAYER - 1) ? dout : nullptr);
    }

    k_pool_zero<<<(BMAX * HID + 255) / 256, 256>>>();
    k_pool<<<((size_t)M * 32 + 255) / 256, 256>>>(batch, M);
    k_write_pool<<<(out_size - M * HID + 255) / 256, 256>>>(dout, M, out_size - M * HID);
}

// round 6
// speedup vs baseline: 1.5021x; 1.0753x over previous
#include <cuda_runtime.h>
#include <cuda_bf16.h>
#include <mma.h>
#include <math.h>

using namespace nvcuda;

#define HID 128
#define NHEAD 4
#define CDIM 128
#define HC 512
#define NLAYER 3
#define NMAX 10240
#define BMAX 64
#define EMAX (160000 + NMAX + 768)

// ---------------- device scratch ----------------
static __device__ __align__(16) float g_h   [(size_t)NMAX * HID];
static __device__ __align__(16) float g_hw  [(size_t)NMAX * HC];
static __device__ __align__(16) __nv_bfloat16 g_Ahi[(size_t)NMAX * HID];
static __device__ __align__(16) __nv_bfloat16 g_Alo[(size_t)NMAX * HID];
static __device__ __align__(16) __nv_bfloat16 g_Whi[(size_t)NLAYER * HID * HC];
static __device__ __align__(16) __nv_bfloat16 g_Wlo[(size_t)NLAYER * HID * HC];
static __device__ __align__(16) float g_asrc[NMAX * NHEAD];
static __device__ __align__(16) float g_adst[NMAX * NHEAD];
static __device__ __align__(16) float g_gmax[NHEAD];
static __device__ __align__(16) float g_sum [NMAX * NHEAD];     // denom -> rinv (in place)
static __device__ __align__(16) float g_expv[(size_t)EMAX * 4]; // per-edge exp numerators
static __device__ __align__(16) float g_out [(size_t)NMAX * HID];
static __device__ __align__(16) float g_pool[BMAX * HID];
static __device__ float g_cnt [BMAX];
static __device__ int   g_is64;
// CSR by src
static __device__ int g_deg[NMAX];
static __device__ int g_ptr[NMAX];
static __device__ int g_cur[NMAX];
static __device__ int g_adj[EMAX];

// ---------------- helpers ----------------
__device__ __forceinline__ float lrelu(float x) { return x > 0.f ? x : 0.2f * x; }

__device__ __forceinline__ void atomicMaxF(float* a, float v) {
    if (v >= 0.f) atomicMax((int*)a, __float_as_int(v));
    else          atomicMin((unsigned int*)a, __float_as_uint(v));
}

__device__ __forceinline__ void redAdd4(float* p, float4 v) {
    asm volatile("red.global.add.v4.f32 [%0], {%1,%2,%3,%4};"
                 :: "l"(p), "f"(v.x), "f"(v.y), "f"(v.z), "f"(v.w) : "memory");
}

__device__ __forceinline__ void redAdd1(float* p, float v) {
    asm volatile("red.global.add.f32 [%0], %1;" :: "l"(p), "f"(v) : "memory");
}

__device__ __forceinline__ int idx_at(const void* p, int i, int is64) {
    return is64 ? (int)((const long long*)p)[i] : ((const int*)p)[i];
}

// ---------------- CSR build ----------------
// zero degrees + detect index dtype (thread 0)
__global__ void k_csr0(const void* ei, int M) {
    int i = blockIdx.x * blockDim.x + threadIdx.x;
    if (i < M) g_deg[i] = 0;
    if (i == 0) {
        const long long* p = (const long long*)ei;
        int ok = 1;
        for (int k = 0; k < 16; k++) {
            long long v = p[k];
            if (v < 0 || v >= (long long)M) { ok = 0; break; }
        }
        g_is64 = ok;
    }
}

__global__ void k_hist(const void* __restrict__ ei, int E, int M) {
    int i = blockIdx.x * blockDim.x + threadIdx.x;
    if (i >= E + M) return;
    int s = (i < E) ? idx_at(ei, i, g_is64) : (i - E);
    atomicAdd(&g_deg[s], 1);
}

// single-block shfl-scan: 1024 threads, register-resident chunks
__global__ void k_scan(int M) {
    __shared__ int ws[32];
    int t = threadIdx.x;
    int chunk = (M + 1023) >> 10;        // <= 16 for M <= 16384
    int start = t * chunk;
    int loc[16];
    int sum = 0;
#pragma unroll 16
    for (int i = 0; i < chunk; i++) {
        int idx = start + i;
        int v = (idx < M) ? g_deg[idx] : 0;
        loc[i] = sum;
        sum += v;
    }
    int lane = t & 31, wid = t >> 5;
    int x = sum;
#pragma unroll
    for (int o = 1; o < 32; o <<= 1) {
        int y = __shfl_up_sync(~0u, x, o);
        if (lane >= o) x += y;
    }
    if (lane == 31) ws[wid] = x;
    __syncthreads();
    if (wid == 0) {
        int y = ws[lane];
#pragma unroll
        for (int o = 1; o < 32; o <<= 1) {
            int z = __shfl_up_sync(~0u, y, o);
            if (lane >= o) y += z;
        }
        ws[lane] = y;
    }
    __syncthreads();
    int base = (x - sum) + (wid ? ws[wid - 1] : 0);
#pragma unroll 16
    for (int i = 0; i < chunk; i++) {
        int idx = start + i;
        if (idx < M) {
            int p = base + loc[i];
            g_ptr[idx] = p;
            g_cur[idx] = p;
        }
    }
}

__global__ void k_fill(const void* __restrict__ ei, int E, int M) {
    int i = blockIdx.x * blockDim.x + threadIdx.x;
    if (i >= E + M) return;
    int is64 = g_is64;
    int s, d;
    if (i < E) { s = idx_at(ei, i, is64); d = idx_at(ei, E + i, is64); } else { s = d = i - E; }
    int pos = atomicAdd(&g_cur[s], 1);
    g_adj[pos] = d;
}

// ---------------- main kernels ----------------

// h0 = relu(x @ node_W + node_b); bf16 split; zero g_out/g_sum/gmax/pool
__global__ void k_init(const float* __restrict__ x, const float* __restrict__ W,
                       const float* __restrict__ b, int M) {
    int i = blockIdx.x * blockDim.x + threadIdx.x;
    if (i >= M * HID) return;
    int n = i >> 7, j = i & 127;
    float acc = b[j];
#pragma unroll
    for (int k = 0; k < 5; k++) acc += x[n * 5 + k] * W[k * HID + j];
    float h = fmaxf(acc, 0.f);
    g_h[i] = h;
    __nv_bfloat16 hi = __float2bfloat16(h);
    g_Ahi[i] = hi;
    g_Alo[i] = __float2bfloat16(h - __bfloat162float(hi));
    g_out[i] = 0.f;
    if (i < M * NHEAD) g_sum[i] = 0.f;
    if (i < NHEAD) g_gmax[i] = -1e30f;
    if (i < BMAX * HID) g_pool[i] = 0.f;
    if (i < BMAX) g_cnt[i] = 0.f;
}

__global__ void k_convW(const float* __restrict__ Ws) {
    int i = blockIdx.x * blockDim.x + threadIdx.x;
    if (i >= NLAYER * HID * HC) return;
    float w = Ws[i];
    __nv_bfloat16 hi = __float2bfloat16(w);
    g_Whi[i] = hi;
    g_Wlo[i] = __float2bfloat16(w - __bfloat162float(hi));
}

// GEMM 64(M) x 128(N=head), smem-staged bf16x3 wmma + fused attention epilogue
__global__ void k_gemm(const __nv_bfloat16* __restrict__ Whi,
                       const __nv_bfloat16* __restrict__ Wlo,
                       const float* __restrict__ att_src,
                       const float* __restrict__ att_dst, int M) {
    __shared__ __align__(16) unsigned char sm_raw[64 * 132 * 4];
    __nv_bfloat16* Ahi = (__nv_bfloat16*)sm_raw;                  // [64][48]
    __nv_bfloat16* Alo = Ahi + 64 * 48;
    __nv_bfloat16* Bhi = (__nv_bfloat16*)(sm_raw + 12288);        // [32][136]
    __nv_bfloat16* Blo = Bhi + 32 * 136;
    float* Cs = (float*)sm_raw;                                   // [64][132]

    int head = blockIdx.x;
    int bm = blockIdx.y * 64;
    int tid = threadIdx.x;
    int w = tid >> 5, lane = tid & 31;
    int wm = w & 1, wn = w >> 1;

    wmma::fragment<wmma::accumulator, 16, 16, 16, float> acc[2][2];
#pragma unroll
    for (int i = 0; i < 2; i++)
#pragma unroll
        for (int j = 0; j < 2; j++) wmma::fill_fragment(acc[i][j], 0.f);

    for (int k0 = 0; k0 < 128; k0 += 32) {
        {
            int row = tid >> 2, c8 = (tid & 3) * 8;
            int grow = bm + row;
            uint4 vh = make_uint4(0, 0, 0, 0), vl = make_uint4(0, 0, 0, 0);
            if (grow < M) {
                vh = *(const uint4*)(g_Ahi + (size_t)grow * HID + k0 + c8);
                vl = *(const uint4*)(g_Alo + (size_t)grow * HID + k0 + c8);
            }
            *(uint4*)(Ahi + row * 48 + c8) = vh;
            *(uint4*)(Alo + row * 48 + c8) = vl;
        }
#pragma unroll
        for (int i = 0; i < 2; i++) {
            int idx = tid + i * 256;
            int r = idx >> 4, c8 = (idx & 15) * 8;
            *(uint4*)(Bhi + r * 136 + c8) =
                *(const uint4*)(Whi + (size_t)(k0 + r) * HC + head * 128 + c8);
            *(uint4*)(Blo + r * 136 + c8) =
                *(const uint4*)(Wlo + (size_t)(k0 + r) * HC + head * 128 + c8);
        }
        __syncthreads();
#pragma unroll
        for (int kk = 0; kk < 32; kk += 16) {
            wmma::fragment<wmma::matrix_a, 16, 16, 16, __nv_bfloat16, wmma::row_major> ahi[2], alo[2];
            wmma::fragment<wmma::matrix_b, 16, 16, 16, __nv_bfloat16, wmma::row_major> bhi[2], blo[2];
#pragma unroll
            for (int i = 0; i < 2; i++) {
                wmma::load_matrix_sync(ahi[i], Ahi + (wm * 32 + i * 16) * 48 + kk, 48);
                wmma::load_matrix_sync(alo[i], Alo + (wm * 32 + i * 16) * 48 + kk, 48);
                wmma::load_matrix_sync(bhi[i], Bhi + kk * 136 + wn * 32 + i * 16, 136);
                wmma::load_matrix_sync(blo[i], Blo + kk * 136 + wn * 32 + i * 16, 136);
            }
#pragma unroll
            for (int i = 0; i < 2; i++)
#pragma unroll
                for (int j = 0; j < 2; j++) {
                    wmma::mma_sync(acc[i][j], ahi[i], bhi[j], acc[i][j]);
                    wmma::mma_sync(acc[i][j], ahi[i], blo[j], acc[i][j]);
                    wmma::mma_sync(acc[i][j], alo[i], bhi[j], acc[i][j]);
                }
        }
        __syncthreads();
    }

#pragma unroll
    for (int i = 0; i < 2; i++)
#pragma unroll
        for (int j = 0; j < 2; j++)
            wmma::store_matrix_sync(Cs + (wm * 32 + i * 16) * 132 + wn * 32 + j * 16,
                                    acc[i][j], 132, wmma::mem_row_major);
    __syncthreads();

    float4 as4 = *(const float4*)(att_src + head * CDIM + lane * 4);
    float4 ad4 = *(const float4*)(att_dst + head * CDIM + lane * 4);
#pragma unroll
    for (int r = 0; r < 8; r++) {
        int row = w * 8 + r;
        int grow = bm + row;
        if (grow >= M) break;
        float4 c4 = *(float4*)(Cs + row * 132 + lane * 4);
        *(float4*)(g_hw + (size_t)grow * HC + head * CDIM + lane * 4) = c4;
        float ss = c4.x * as4.x + c4.y * as4.y + c4.z * as4.z + c4.w * as4.w;
        float sd = c4.x * ad4.x + c4.y * ad4.y + c4.z * ad4.z + c4.w * ad4.w;
#pragma unroll
        for (int o = 16; o; o >>= 1) {
            ss += __shfl_xor_sync(~0u, ss, o);
            sd += __shfl_xor_sync(~0u, sd, o);
        }
        if (lane == 0) {
            g_asrc[grow * 4 + head] = ss;
            g_adst[grow * 4 + head] = sd;
            atomicMaxF(&g_gmax[head], ss);
        }
    }
}

// CSR pass 1: per-edge exp numerators (stored) + denominator red.add. Warp per src.
__global__ void k_esum(int M) {
    int gid = blockIdx.x * blockDim.x + threadIdx.x;
    int s = gid >> 5, lane = gid & 31;
    if (s >= M) return;
    float4 gm = *(const float4*)g_gmax;
    float4 as = *(const float4*)(g_asrc + s * 4);
    int base = g_ptr[s], cnt = g_deg[s];
    for (int j = lane; j < cnt; j += 32) {
        int d = g_adj[base + j];
        float4 ad = *(const float4*)(g_adst + d * 4);
        float4 ev;
        ev.x = __expf(lrelu(as.x + ad.x) - lrelu(gm.x + ad.x));
        ev.y = __expf(lrelu(as.y + ad.y) - lrelu(gm.y + ad.y));
        ev.z = __expf(lrelu(as.z + ad.z) - lrelu(gm.z + ad.z));
        ev.w = __expf(lrelu(as.w + ad.w) - lrelu(gm.w + ad.w));
        *(float4*)(g_expv + (size_t)(base + j) * 4) = ev;
        redAdd4(g_sum + d * 4, ev);
    }
}

// invert denominators once per (node,head); fold 1/NHEAD
__global__ void k_rinv(int M) {
    int i = blockIdx.x * blockDim.x + threadIdx.x;
    if (i >= M * NHEAD) return;
    g_sum[i] = 0.25f / (g_sum[i] + 1e-16f);
}

// CSR pass 2: aggregate. Warp per src; no MUFU.
__global__ void k_acc(int M) {
    int gid = blockIdx.x * blockDim.x + threadIdx.x;
    int s = gid >> 5, lane = gid & 31;
    if (s >= M) return;
    const float4* hs = (const float4*)(g_hw + (size_t)s * HC);
    float4 v0 = hs[lane];
    float4 v1 = hs[32 + lane];
    float4 v2 = hs[64 + lane];
    float4 v3 = hs[96 + lane];
    int base = g_ptr[s], cnt = g_deg[s];
    for (int j0 = 0; j0 < cnt; j0 += 32) {
        int j = j0 + lane;
        int d = 0;
        float a0 = 0.f, a1 = 0.f, a2 = 0.f, a3 = 0.f;
        if (j < cnt) {
            d = g_adj[base + j];
            float4 ev = *(const float4*)(g_expv + (size_t)(base + j) * 4);
            float4 ri = *(const float4*)(g_sum + d * 4);
            a0 = ev.x * ri.x; a1 = ev.y * ri.y; a2 = ev.z * ri.z; a3 = ev.w * ri.w;
        }
        int m = min(cnt - j0, 32);
        for (int jj = 0; jj < m; jj++) {
            int dd  = __shfl_sync(~0u, d, jj);
            float b0 = __shfl_sync(~0u, a0, jj);
            float b1 = __shfl_sync(~0u, a1, jj);
            float b2 = __shfl_sync(~0u, a2, jj);
            float b3 = __shfl_sync(~0u, a3, jj);
            float4 r;
            r.x = b0 * v0.x + b1 * v1.x + b2 * v2.x + b3 * v3.x;
            r.y = b0 * v0.y + b1 * v1.y + b2 * v2.y + b3 * v3.y;
            r.z = b0 * v0.z + b1 * v1.z + b2 * v2.z + b3 * v3.z;
            r.w = b0 * v0.w + b1 * v1.w + b2 * v2.w + b3 * v3.w;
            redAdd4(g_out + (size_t)dd * HID + lane * 4, r);
        }
    }
}

// bias + LN + relu + residual + next-layer prep; final layer also pools + writes out
__global__ void k_post(const float* __restrict__ bias, const float* __restrict__ lng,
                       const float* __restrict__ lnb, int M, float* __restrict__ dout,
                       const void* __restrict__ batch) {
    int n = blockIdx.x;
    if (n >= M) return;
    int t = threadIdx.x;
    size_t i = (size_t)n * HID + t;
    float v = g_out[i] + bias[t];
    __shared__ float sh[4];
    float s = v;
#pragma unroll
    for (int o = 16; o; o >>= 1) s += __shfl_xor_sync(~0u, s, o);
    if ((t & 31) == 0) sh[t >> 5] = s;
    __syncthreads();
    float mu = (sh[0] + sh[1] + sh[2] + sh[3]) * (1.f / 128.f);
    __syncthreads();
    float dv = v - mu;
    float q = dv * dv;
#pragma unroll
    for (int o = 16; o; o >>= 1) q += __shfl_xor_sync(~0u, q, o);
    if ((t & 31) == 0) sh[t >> 5] = q;
    __syncthreads();
    float var = (sh[0] + sh[1] + sh[2] + sh[3]) * (1.f / 128.f);
    float ln = dv * rsqrtf(var + 1e-5f) * lng[t] + lnb[t];
    float h = g_h[i] + fmaxf(ln, 0.f);
    g_h[i] = h;
    if (!dout) {
        __nv_bfloat16 hi = __float2bfloat16(h);
        g_Ahi[i] = hi;
        g_Alo[i] = __float2bfloat16(h - __bfloat162float(hi));
        g_out[i] = 0.f;
        if (t < NHEAD) g_sum[n * NHEAD + t] = 0.f;
        if (n == 0 && t < NHEAD) g_gmax[t] = -1e30f;
    } else {
        dout[i] = h;
        int b = idx_at(batch, n, g_is64);
        redAdd1(g_pool + b * HID + t, h);
        if (t == 0) redAdd1(g_cnt + b, 1.f);
    }
}

__global__ void k_write_pool(float* __restrict__ dout, int M, int tail) {
    int i = blockIdx.x * blockDim.x + threadIdx.x;
    if (i >= tail) return;
    dout[(size_t)M * HID + i] = g_pool[i] / fmaxf(g_cnt[i >> 7], 1.f);
}

// ---------------- launch ----------------
extern "C" void kernel_launch(void* const* d_in, const int* in_sizes, int n_in,
                              void* d_out, int out_size) {
    const float* x        = (const float*)d_in[0];
    const void*  ei       = d_in[1];
    const void*  batch    = d_in[2];
    const float* node_W   = (const float*)d_in[3];
    const float* node_b   = (const float*)d_in[4];
    const float* Ws       = (const float*)d_in[5];
    const float* att_srcs = (const float*)d_in[6];
    const float* att_dsts = (const float*)d_in[7];
    const float* biases   = (const float*)d_in[8];
    const float* ln_gs    = (const float*)d_in[9];
    const float* ln_bs    = (const float*)d_in[10];

    int M = in_sizes[2];
    int E = in_sizes[1] / 2;
    int EM = E + M;
    float* dout = (float*)d_out;

    k_csr0<<<(M + 255) / 256, 256>>>(ei, M);
    k_hist<<<(EM + 255) / 256, 256>>>(ei, E, M);
    k_scan<<<1, 1024>>>(M);
    k_fill<<<(EM + 255) / 256, 256>>>(ei, E, M);

    k_init<<<(M * HID + 255) / 256, 256>>>(x, node_W, node_b, M);
    k_convW<<<(NLAYER * HID * HC + 255) / 256, 256>>>(Ws);

    __nv_bfloat16* whi_base;
    __nv_bfloat16* wlo_base;
    cudaGetSymbolAddress((void**)&whi_base, g_Whi);
    cudaGetSymbolAddress((void**)&wlo_base, g_Wlo);

    for (int l = 0; l < NLAYER; l++) {
        k_gemm<<<dim3(NHEAD, (M + 63) / 64), 256>>>(whi_base + (size_t)l * HID * HC,
                                                    wlo_base + (size_t)l * HID * HC,
                                                    att_srcs + l * HC, att_dsts + l * HC, M);
        k_esum<<<((size_t)M * 32 + 255) / 256, 256>>>(M);
        k_rinv<<<(M * NHEAD + 255) / 256, 256>>>(M);
        k_acc<<<((size_t)M * 32 + 255) / 256, 256>>>(M);
        k_post<<<M, 128>>>(biases + l * HID, ln_gs + l * HID, ln_bs + l * HID, M,
                           (l == NLAYER - 1) ? dout : nullptr, batch);
    }

    k_write_pool<<<(out_size - M * HID + 255) / 256, 256>>>(dout, M, out_size - M * HID);
}